// round 13
// baseline (speedup 1.0000x reference)
#include <cuda_runtime.h>
#include <math.h>

#define NIMG 8
#define CINC 32
#define HH 64
#define WW 64
#define INTER 64
#define BCC 108
#define KS 7
#define NBAS 6
#define TBAS 18
#define OUTC 64
#define NPIX (HH*WW)          // 4096
#define MTOT (NIMG*NPIX)      // 32768
#define EPSV 1e-5f
#define XSTR 47               // atoms xt channel-row stride (conflict-free)

typedef unsigned long long ull;

// ---------------- f32x2 packed-FMA helpers (sm_103a) -----------------------
__device__ __forceinline__ ull pack2(float lo, float hi) {
    ull r; asm("mov.b64 %0,{%1,%2};" : "=l"(r) : "f"(lo), "f"(hi)); return r;
}
__device__ __forceinline__ void unpack2(ull v, float& lo, float& hi) {
    asm("mov.b64 {%0,%1},%2;" : "=f"(lo), "=f"(hi) : "l"(v));
}
__device__ __forceinline__ ull ffma2(ull a, ull b, ull c) {
    ull d; asm("fma.rn.f32x2 %0,%1,%2,%3;" : "=l"(d) : "l"(a), "l"(b), "l"(c));
    return d;
}

// ---------------- scratch ---------------------------------------------------
__device__ float g_y1[NIMG*INTER*NPIX];        // conv1 out; bn_tanh'd in place
__device__ float g_y2[NIMG*BCC*NPIX];          // conv2 out; bn_tanh'd in place
__device__ float g_ab1[2*INTER];
__device__ float g_ab2[2*BCC];
__device__ float g_bout[(long)MTOT*CINC*NBAS];

// ======================= conv1: 32ch -> 64ch, 3x3 pad1 ======================
// 128 thr; tile 32 wide x 8 tall; thread = 1x2 vertical strip x 16 out-ch.
__global__ __launch_bounds__(128, 6) void conv1_ker(const float* __restrict__ x,
                                                    const float* __restrict__ w,
                                                    const float* __restrict__ b) {
    __shared__ __align__(16) float xt[8*340];      // [ci][10 rows][34 cols]
    __shared__ __align__(16) float wt[8*144];      // [ci][j][16co]
    const int n   = blockIdx.z >> 2;
    const int cg  = blockIdx.z & 3;
    const int co0 = cg * 16;
    const int bx = blockIdx.x * 32;
    const int by = blockIdx.y * 8;
    const int tid = threadIdx.x;
    const int px  = tid & 31;
    const int py0 = (tid >> 5) * 2;

    ull acc[2][8];
#pragma unroll
    for (int s = 0; s < 2; s++)
#pragma unroll
        for (int q = 0; q < 8; q++) acc[s][q] = 0ull;

    for (int ch = 0; ch < CINC; ch += 8) {
        for (int i = tid; i < 8*340; i += 128) {
            int ci = i / 340, rem = i % 340;
            int yy = rem / 34, xx = rem % 34;
            int gy = by + yy - 1, gx = bx + xx - 1;
            float v = 0.f;
            if (gy >= 0 && gy < HH && gx >= 0 && gx < WW)
                v = x[((n*CINC + ch + ci)*HH + gy)*WW + gx];
            xt[i] = v;
        }
        for (int i = tid; i < 8*144; i += 128) {
            int ci = i / 144, rem = i % 144;
            int j = rem >> 4, col = rem & 15;
            wt[i] = w[((co0 + col)*CINC + ch + ci)*9 + j];
        }
        __syncthreads();

#pragma unroll
        for (int ci = 0; ci < 8; ci++) {
            const int base = ci*340 + py0*34 + px;
            float xs[12];
#pragma unroll
            for (int r = 0; r < 4; r++)
#pragma unroll
                for (int c = 0; c < 3; c++)
                    xs[r*3+c] = xt[base + r*34 + c];
#pragma unroll
            for (int j = 0; j < 9; j++) {
                const int dy = j / 3, dx = j % 3;
                const ulonglong2* wp = (const ulonglong2*)&wt[ci*144 + j*16];
                ulonglong2 u0 = wp[0], u1 = wp[1], u2 = wp[2], u3 = wp[3];
#pragma unroll
                for (int s = 0; s < 2; s++) {
                    float v = xs[(s+dy)*3 + dx];
                    ull xv = pack2(v, v);
                    acc[s][0] = ffma2(u0.x, xv, acc[s][0]);
                    acc[s][1] = ffma2(u0.y, xv, acc[s][1]);
                    acc[s][2] = ffma2(u1.x, xv, acc[s][2]);
                    acc[s][3] = ffma2(u1.y, xv, acc[s][3]);
                    acc[s][4] = ffma2(u2.x, xv, acc[s][4]);
                    acc[s][5] = ffma2(u2.y, xv, acc[s][5]);
                    acc[s][6] = ffma2(u3.x, xv, acc[s][6]);
                    acc[s][7] = ffma2(u3.y, xv, acc[s][7]);
                }
            }
        }
        __syncthreads();
    }
#pragma unroll
    for (int s = 0; s < 2; s++) {
        const int gy = by + py0 + s;
#pragma unroll
        for (int q = 0; q < 8; q++) {
            int co = co0 + 2*q;
            float lo, hi; unpack2(acc[s][q], lo, hi);
            g_y1[((n*INTER + co  )*HH + gy)*WW + bx + px] = lo + b[co];
            g_y1[((n*INTER + co+1)*HH + gy)*WW + bx + px] = hi + b[co+1];
        }
    }
}

// ======================= conv2: 64ch -> 108ch, 3x3 pad1 =====================
__global__ __launch_bounds__(128, 6) void conv2_ker(const float* __restrict__ w,
                                                    const float* __restrict__ b) {
    __shared__ __align__(16) float xt[8*340];
    __shared__ __align__(16) float wt[8*144];
    const int n   = blockIdx.z / 7;
    const int cg  = blockIdx.z % 7;
    const int co0 = cg * 16;
    const int bx = blockIdx.x * 32;
    const int by = blockIdx.y * 8;
    const int tid = threadIdx.x;
    const int px  = tid & 31;
    const int py0 = (tid >> 5) * 2;

    ull acc[2][8];
#pragma unroll
    for (int s = 0; s < 2; s++)
#pragma unroll
        for (int q = 0; q < 8; q++) acc[s][q] = 0ull;

    for (int ch = 0; ch < INTER; ch += 8) {
        for (int i = tid; i < 8*340; i += 128) {
            int ci = i / 340, rem = i % 340;
            int yy = rem / 34, xx = rem % 34;
            int gy = by + yy - 1, gx = bx + xx - 1;
            float v = 0.f;
            if (gy >= 0 && gy < HH && gx >= 0 && gx < WW)
                v = g_y1[((n*INTER + ch + ci)*HH + gy)*WW + gx];
            xt[i] = v;
        }
        for (int i = tid; i < 8*144; i += 128) {
            int ci = i / 144, rem = i % 144;
            int j = rem >> 4, col = rem & 15;
            wt[i] = (co0 + col < BCC) ? w[((co0 + col)*INTER + ch + ci)*9 + j] : 0.f;
        }
        __syncthreads();

#pragma unroll
        for (int ci = 0; ci < 8; ci++) {
            const int base = ci*340 + py0*34 + px;
            float xs[12];
#pragma unroll
            for (int r = 0; r < 4; r++)
#pragma unroll
                for (int c = 0; c < 3; c++)
                    xs[r*3+c] = xt[base + r*34 + c];
#pragma unroll
            for (int j = 0; j < 9; j++) {
                const int dy = j / 3, dx = j % 3;
                const ulonglong2* wp = (const ulonglong2*)&wt[ci*144 + j*16];
                ulonglong2 u0 = wp[0], u1 = wp[1], u2 = wp[2], u3 = wp[3];
#pragma unroll
                for (int s = 0; s < 2; s++) {
                    float v = xs[(s+dy)*3 + dx];
                    ull xv = pack2(v, v);
                    acc[s][0] = ffma2(u0.x, xv, acc[s][0]);
                    acc[s][1] = ffma2(u0.y, xv, acc[s][1]);
                    acc[s][2] = ffma2(u1.x, xv, acc[s][2]);
                    acc[s][3] = ffma2(u1.y, xv, acc[s][3]);
                    acc[s][4] = ffma2(u2.x, xv, acc[s][4]);
                    acc[s][5] = ffma2(u2.y, xv, acc[s][5]);
                    acc[s][6] = ffma2(u3.x, xv, acc[s][6]);
                    acc[s][7] = ffma2(u3.y, xv, acc[s][7]);
                }
            }
        }
        __syncthreads();
    }
#pragma unroll
    for (int s = 0; s < 2; s++) {
        const int gy = by + py0 + s;
#pragma unroll
        for (int q = 0; q < 8; q++) {
            int co = co0 + 2*q;
            float lo, hi; unpack2(acc[s][q], lo, hi);
            if (co < BCC)
                g_y2[((n*BCC + co  )*HH + gy)*WW + bx + px] = lo + b[co];
            if (co + 1 < BCC)
                g_y2[((n*BCC + co+1)*HH + gy)*WW + bx + px] = hi + b[co+1];
        }
    }
}

// ---------------- BN stats: one kernel per layer (grid = CH) ---------------
template<int CH, int WHICH>
__global__ __launch_bounds__(256) void stats_one(const float* __restrict__ gam,
                                                 const float* __restrict__ bet) {
    const float* y = (WHICH == 0) ? g_y1 : g_y2;
    float* ab      = (WHICH == 0) ? g_ab1 : g_ab2;
    const int c = blockIdx.x;
    const int tid = threadIdx.x;
    float s = 0.f, s2 = 0.f;
#pragma unroll
    for (int n = 0; n < NIMG; n++) {
        const float4* p4 = (const float4*)&y[(size_t)(n*CH + c)*NPIX];
#pragma unroll
        for (int k = 0; k < 4; k++) {
            float4 f = p4[k*256 + tid];
            s  += (f.x + f.y) + (f.z + f.w);
            s2 += (f.x*f.x + f.y*f.y) + (f.z*f.z + f.w*f.w);
        }
    }
    __shared__ float sh[256], sh2[256];
    sh[tid] = s; sh2[tid] = s2;
    __syncthreads();
    for (int st = 128; st > 0; st >>= 1) {
        if (tid < st) { sh[tid] += sh[tid+st]; sh2[tid] += sh2[tid+st]; }
        __syncthreads();
    }
    if (tid == 0) {
        float mean = sh[0] * (1.f/(float)MTOT);
        float var  = sh2[0] * (1.f/(float)MTOT) - mean*mean;
        float a = gam[c] * rsqrtf(var + EPSV);
        ab[2*c]   = a;
        ab[2*c+1] = bet[c] - mean * a;
    }
}

// ---------------- y = tanh(a*y + b) in place; one block per (n,c) ----------
template<int CH, int WHICH>
__global__ __launch_bounds__(256) void bn_tanh_ker() {
    float* y = (WHICH == 0) ? g_y1 : g_y2;
    const float* ab = (WHICH == 0) ? g_ab1 : g_ab2;
    const int c = blockIdx.x % CH;
    const float a = ab[2*c], b = ab[2*c+1];
    float4* p4 = (float4*)y + (size_t)blockIdx.x * 1024;
#pragma unroll
    for (int k = 0; k < 4; k++) {
        float4 f = p4[k*256 + threadIdx.x];
        f.x = tanhf(fmaf(a, f.x, b));
        f.y = tanhf(fmaf(a, f.y, b));
        f.z = tanhf(fmaf(a, f.z, b));
        f.w = tanhf(fmaf(a, f.w, b));
        p4[k*256 + threadIdx.x] = f;
    }
}

// -------- fused: coef -> atoms -> 7x7 patch contraction --------------------
// smem union: coef (phase B input) and xt (phase C input) share storage;
// xt is staged AFTER phase B. xt stride 47 -> conflict-free phase C loads.
__global__ __launch_bounds__(256) void atoms_ker(const float* __restrict__ x,
                                                 const float* __restrict__ bases) {
    __shared__ __align__(16) float atm [16*49*6];   // 18.8 KB
    __shared__ __align__(16) float bs2 [49*TBAS];   //  3.5 KB
    __shared__ __align__(16) float un  [112*XSTR];  // 21.1 KB (coef needs 1728)
    float* coef = un;
    float* xt   = un;
    const int tid = threadIdx.x;
    const int n  = blockIdx.z;
    const int bx = blockIdx.x * 8;
    const int by = blockIdx.y * 2;

    for (int i = tid; i < 49*TBAS; i += 256) {
        int k = i / TBAS, t = i % TBAS;
        bs2[i] = bases[t*49 + k];
    }
    // stage coef (16 px x 108 ch)
    for (int i = tid; i < 16*108; i += 256) {
        int p = i / 108, cc = i % 108;
        int py = p >> 3, px = p & 7;
        coef[i] = g_y2[((n*BCC + cc)*HH + (by+py))*WW + (bx+px)];
    }
    __syncthreads();

    // phase B: atoms[p][k][m] = sum_t coef[p][m*18+t] * bases[t][k]
    for (int i = tid; i < 16*49; i += 256) {
        int p = i / 49, k = i % 49;
        const ull* cf = (const ull*)&coef[p*108];
        const ull* bp = (const ull*)&bs2[k*TBAS];
        ull a[6];
#pragma unroll
        for (int m = 0; m < 6; m++) a[m] = 0ull;
#pragma unroll
        for (int u = 0; u < 9; u++) {
            ull bv = bp[u];
#pragma unroll
            for (int m = 0; m < 6; m++)
                a[m] = ffma2(cf[m*9 + u], bv, a[m]);
        }
        float* ap = &atm[(p*49 + k)*6];
#pragma unroll
        for (int m = 0; m < 6; m++) {
            float lo, hi; unpack2(a[m], lo, hi);
            ap[m] = lo + hi;
        }
    }
    __syncthreads();

    // stage xt (overwrites coef): 14x8 halo x 32 ch, stride XSTR
    for (int i = tid; i < 32*112; i += 256) {
        int c = i / 112, pos = i % 112;
        int yy = pos / 14, xx = pos % 14;
        int gy = by + yy - 3, gx = bx + xx - 3;
        float v = 0.f;
        if (gy >= 0 && gy < HH && gx >= 0 && gx < WW)
            v = x[((n*CINC + c)*HH + gy)*WW + gx];
        xt[pos*XSTR + c] = v;
    }
    __syncthreads();

    // phase C: thread = (pixel pg, channels {cl, cl+16}); 6 m each.
    {
        const int pg = tid >> 4, cl = tid & 15;
        const int py = pg >> 3, px = pg & 7;
        const float* ab_ = &atm[pg*49*6];
        const float* xb  = &xt[(py*14 + px)*XSTR];
        ull a0[3], a1[3];
#pragma unroll
        for (int m = 0; m < 3; m++) { a0[m] = 0ull; a1[m] = 0ull; }
#pragma unroll
        for (int ky = 0; ky < 7; ky++) {
#pragma unroll
            for (int kx = 0; kx < 7; kx++) {
                const int k = ky*7 + kx;
                const int off = (ky*14 + kx)*XSTR;
                float v0 = xb[off + cl];
                float v1 = xb[off + cl + 16];
                ull x0 = pack2(v0, v0);
                ull x1 = pack2(v1, v1);
                const ull* ap = (const ull*)&ab_[k*6];
                ull p0 = ap[0], p1 = ap[1], p2 = ap[2];
                a0[0] = ffma2(p0, x0, a0[0]);
                a0[1] = ffma2(p1, x0, a0[1]);
                a0[2] = ffma2(p2, x0, a0[2]);
                a1[0] = ffma2(p0, x1, a1[0]);
                a1[1] = ffma2(p1, x1, a1[1]);
                a1[2] = ffma2(p2, x1, a1[2]);
            }
        }
        const int gy = by + py, gx = bx + px;
        const long pix = (long)n*NPIX + gy*WW + gx;
        ull* op0 = (ull*)&g_bout[pix*192 + cl*6];
        op0[0] = a0[0]; op0[1] = a0[1]; op0[2] = a0[2];
        ull* op1 = (ull*)&g_bout[pix*192 + (cl+16)*6];
        op1[0] = a1[0]; op1[1] = a1[1]; op1[2] = a1[2];
    }
}

// ---------------- out projection: out = W(64,192) . bout + b ---------------
__global__ __launch_bounds__(256) void out_ker(const float* __restrict__ ow,
                                               const float* __restrict__ ob,
                                               float* __restrict__ out) {
    __shared__ __align__(16) float wt2[48*64];   // [dl][o]
    __shared__ __align__(16) float bt[128*49];   // [pix][dl], pad 49
    const int pix0 = blockIdx.x * 128;
    const int tid = threadIdx.x;
    const int pix = tid & 63, og = tid >> 6;

    ull accA[8], accB[8];
#pragma unroll
    for (int i = 0; i < 8; i++) { accA[i] = 0ull; accB[i] = 0ull; }

    for (int ch = 0; ch < 4; ch++) {
        const int d0 = ch * 48;
        for (int i = tid; i < 48*64; i += 256) {
            int dl = i >> 6, o = i & 63;
            wt2[i] = ow[o*192 + d0 + dl];
        }
        for (int i = tid; i < 128*12; i += 256) {
            int p = i / 12, v = i % 12;
            float4 f = ((const float4*)&g_bout[(long)(pix0 + p)*192 + d0])[v];
            float* dst = &bt[p*49 + v*4];
            dst[0] = f.x; dst[1] = f.y; dst[2] = f.z; dst[3] = f.w;
        }
        __syncthreads();
#pragma unroll 4
        for (int dl = 0; dl < 48; dl++) {
            float bvA = bt[pix*49 + dl];
            float bvB = bt[(pix+64)*49 + dl];
            ull bA = pack2(bvA, bvA);
            ull bB = pack2(bvB, bvB);
            const ulonglong2* wp = (const ulonglong2*)&wt2[dl*64 + og*16];
#pragma unroll
            for (int q = 0; q < 4; q++) {
                ulonglong2 u = wp[q];
                accA[2*q  ] = ffma2(u.x, bA, accA[2*q  ]);
                accA[2*q+1] = ffma2(u.y, bA, accA[2*q+1]);
                accB[2*q  ] = ffma2(u.x, bB, accB[2*q  ]);
                accB[2*q+1] = ffma2(u.y, bB, accB[2*q+1]);
            }
        }
        __syncthreads();
    }
    const int n = pix0 >> 12;
    const int remA = (pix0 & 4095) + pix;
    const int remB = remA + 64;
#pragma unroll
    for (int i = 0; i < 8; i++) {
        int o = og*16 + 2*i;
        float lo, hi;
        unpack2(accA[i], lo, hi);
        out[((n*OUTC + o  )*NPIX) + remA] = lo + ob[o];
        out[((n*OUTC + o+1)*NPIX) + remA] = hi + ob[o+1];
        unpack2(accB[i], lo, hi);
        out[((n*OUTC + o  )*NPIX) + remB] = lo + ob[o];
        out[((n*OUTC + o+1)*NPIX) + remB] = hi + ob[o+1];
    }
}

// ---------------------------------------------------------------------------
extern "C" void kernel_launch(void* const* d_in, const int* in_sizes, int n_in,
                              void* d_out, int out_size) {
    const float* x   = (const float*)d_in[0];
    const float* w1  = (const float*)d_in[1];
    const float* b1  = (const float*)d_in[2];
    const float* g1  = (const float*)d_in[3];
    const float* bb1 = (const float*)d_in[4];
    const float* w2  = (const float*)d_in[5];
    const float* b2  = (const float*)d_in[6];
    const float* g2  = (const float*)d_in[7];
    const float* bb2 = (const float*)d_in[8];
    const float* bas = (const float*)d_in[9];
    const float* ow  = (const float*)d_in[10];
    const float* ob  = (const float*)d_in[11];
    float* out = (float*)d_out;

    conv1_ker<<<dim3(2, 8, NIMG*4), 128>>>(x, w1, b1);
    stats_one<INTER, 0><<<INTER, 256>>>(g1, bb1);
    bn_tanh_ker<INTER, 0><<<NIMG*INTER, 256>>>();
    conv2_ker<<<dim3(2, 8, NIMG*7), 128>>>(w2, b2);
    stats_one<BCC, 1><<<BCC, 256>>>(g2, bb2);
    bn_tanh_ker<BCC, 1><<<NIMG*BCC, 256>>>();
    atoms_ker<<<dim3(8, 32, NIMG), 256>>>(x, bas);
    out_ker<<<256, 256>>>(ow, ob, out);
}

// round 14
// speedup vs baseline: 1.0326x; 1.0326x over previous
#include <cuda_runtime.h>
#include <math.h>

#define NIMG 8
#define CINC 32
#define HH 64
#define WW 64
#define INTER 64
#define BCC 108
#define KS 7
#define NBAS 6
#define TBAS 18
#define OUTC 64
#define NPIX (HH*WW)          // 4096
#define MTOT (NIMG*NPIX)      // 32768
#define EPSV 1e-5f
#define XSTR 47               // atoms xt channel-row stride (conflict-free)

typedef unsigned long long ull;

// ---------------- f32x2 packed-FMA helpers (sm_103a) -----------------------
__device__ __forceinline__ ull pack2(float lo, float hi) {
    ull r; asm("mov.b64 %0,{%1,%2};" : "=l"(r) : "f"(lo), "f"(hi)); return r;
}
__device__ __forceinline__ void unpack2(ull v, float& lo, float& hi) {
    asm("mov.b64 {%0,%1},%2;" : "=f"(lo), "=f"(hi) : "l"(v));
}
__device__ __forceinline__ ull ffma2(ull a, ull b, ull c) {
    ull d; asm("fma.rn.f32x2 %0,%1,%2,%3;" : "=l"(d) : "l"(a), "l"(b), "l"(c));
    return d;
}

// ---------------- scratch ---------------------------------------------------
__device__ float g_y1[NIMG*INTER*NPIX];        // conv1 out; bn_tanh'd in place
__device__ float g_y2[NIMG*BCC*NPIX];          // conv2 out; bn_tanh'd in place
__device__ float g_ab1[2*INTER];
__device__ float g_ab2[2*BCC];
__device__ float g_part[2*BCC*NIMG];
__device__ float g_bout[(long)MTOT*CINC*NBAS];

// ======================= conv1: 32ch -> 64ch, 3x3 pad1 ======================
__global__ __launch_bounds__(128, 6) void conv1_ker(const float* __restrict__ x,
                                                    const float* __restrict__ w,
                                                    const float* __restrict__ b) {
    __shared__ __align__(16) float xt[8*340];      // [ci][10 rows][34 cols]
    __shared__ __align__(16) float wt[8*144];      // [ci][j][16co]
    const int n   = blockIdx.z >> 2;
    const int cg  = blockIdx.z & 3;
    const int co0 = cg * 16;
    const int bx = blockIdx.x * 32;
    const int by = blockIdx.y * 8;
    const int tid = threadIdx.x;
    const int px  = tid & 31;
    const int py0 = (tid >> 5) * 2;

    ull acc[2][8];
#pragma unroll
    for (int s = 0; s < 2; s++)
#pragma unroll
        for (int q = 0; q < 8; q++) acc[s][q] = 0ull;

    for (int ch = 0; ch < CINC; ch += 8) {
        for (int i = tid; i < 8*340; i += 128) {
            int ci = i / 340, rem = i % 340;
            int yy = rem / 34, xx = rem % 34;
            int gy = by + yy - 1, gx = bx + xx - 1;
            float v = 0.f;
            if (gy >= 0 && gy < HH && gx >= 0 && gx < WW)
                v = x[((n*CINC + ch + ci)*HH + gy)*WW + gx];
            xt[i] = v;
        }
        for (int i = tid; i < 8*144; i += 128) {
            int ci = i / 144, rem = i % 144;
            int j = rem >> 4, col = rem & 15;
            wt[i] = w[((co0 + col)*CINC + ch + ci)*9 + j];
        }
        __syncthreads();

#pragma unroll
        for (int ci = 0; ci < 8; ci++) {
            const int base = ci*340 + py0*34 + px;
            float xs[12];
#pragma unroll
            for (int r = 0; r < 4; r++)
#pragma unroll
                for (int c = 0; c < 3; c++)
                    xs[r*3+c] = xt[base + r*34 + c];
#pragma unroll
            for (int j = 0; j < 9; j++) {
                const int dy = j / 3, dx = j % 3;
                const ulonglong2* wp = (const ulonglong2*)&wt[ci*144 + j*16];
                ulonglong2 u0 = wp[0], u1 = wp[1], u2 = wp[2], u3 = wp[3];
#pragma unroll
                for (int s = 0; s < 2; s++) {
                    float v = xs[(s+dy)*3 + dx];
                    ull xv = pack2(v, v);
                    acc[s][0] = ffma2(u0.x, xv, acc[s][0]);
                    acc[s][1] = ffma2(u0.y, xv, acc[s][1]);
                    acc[s][2] = ffma2(u1.x, xv, acc[s][2]);
                    acc[s][3] = ffma2(u1.y, xv, acc[s][3]);
                    acc[s][4] = ffma2(u2.x, xv, acc[s][4]);
                    acc[s][5] = ffma2(u2.y, xv, acc[s][5]);
                    acc[s][6] = ffma2(u3.x, xv, acc[s][6]);
                    acc[s][7] = ffma2(u3.y, xv, acc[s][7]);
                }
            }
        }
        __syncthreads();
    }
#pragma unroll
    for (int s = 0; s < 2; s++) {
        const int gy = by + py0 + s;
#pragma unroll
        for (int q = 0; q < 8; q++) {
            int co = co0 + 2*q;
            float lo, hi; unpack2(acc[s][q], lo, hi);
            g_y1[((n*INTER + co  )*HH + gy)*WW + bx + px] = lo + b[co];
            g_y1[((n*INTER + co+1)*HH + gy)*WW + bx + px] = hi + b[co+1];
        }
    }
}

// ======================= conv2: 64ch -> 108ch, 3x3 pad1 =====================
__global__ __launch_bounds__(128, 6) void conv2_ker(const float* __restrict__ w,
                                                    const float* __restrict__ b) {
    __shared__ __align__(16) float xt[8*340];
    __shared__ __align__(16) float wt[8*144];
    const int n   = blockIdx.z / 7;
    const int cg  = blockIdx.z % 7;
    const int co0 = cg * 16;
    const int bx = blockIdx.x * 32;
    const int by = blockIdx.y * 8;
    const int tid = threadIdx.x;
    const int px  = tid & 31;
    const int py0 = (tid >> 5) * 2;

    ull acc[2][8];
#pragma unroll
    for (int s = 0; s < 2; s++)
#pragma unroll
        for (int q = 0; q < 8; q++) acc[s][q] = 0ull;

    for (int ch = 0; ch < INTER; ch += 8) {
        for (int i = tid; i < 8*340; i += 128) {
            int ci = i / 340, rem = i % 340;
            int yy = rem / 34, xx = rem % 34;
            int gy = by + yy - 1, gx = bx + xx - 1;
            float v = 0.f;
            if (gy >= 0 && gy < HH && gx >= 0 && gx < WW)
                v = g_y1[((n*INTER + ch + ci)*HH + gy)*WW + gx];
            xt[i] = v;
        }
        for (int i = tid; i < 8*144; i += 128) {
            int ci = i / 144, rem = i % 144;
            int j = rem >> 4, col = rem & 15;
            wt[i] = (co0 + col < BCC) ? w[((co0 + col)*INTER + ch + ci)*9 + j] : 0.f;
        }
        __syncthreads();

#pragma unroll
        for (int ci = 0; ci < 8; ci++) {
            const int base = ci*340 + py0*34 + px;
            float xs[12];
#pragma unroll
            for (int r = 0; r < 4; r++)
#pragma unroll
                for (int c = 0; c < 3; c++)
                    xs[r*3+c] = xt[base + r*34 + c];
#pragma unroll
            for (int j = 0; j < 9; j++) {
                const int dy = j / 3, dx = j % 3;
                const ulonglong2* wp = (const ulonglong2*)&wt[ci*144 + j*16];
                ulonglong2 u0 = wp[0], u1 = wp[1], u2 = wp[2], u3 = wp[3];
#pragma unroll
                for (int s = 0; s < 2; s++) {
                    float v = xs[(s+dy)*3 + dx];
                    ull xv = pack2(v, v);
                    acc[s][0] = ffma2(u0.x, xv, acc[s][0]);
                    acc[s][1] = ffma2(u0.y, xv, acc[s][1]);
                    acc[s][2] = ffma2(u1.x, xv, acc[s][2]);
                    acc[s][3] = ffma2(u1.y, xv, acc[s][3]);
                    acc[s][4] = ffma2(u2.x, xv, acc[s][4]);
                    acc[s][5] = ffma2(u2.y, xv, acc[s][5]);
                    acc[s][6] = ffma2(u3.x, xv, acc[s][6]);
                    acc[s][7] = ffma2(u3.y, xv, acc[s][7]);
                }
            }
        }
        __syncthreads();
    }
#pragma unroll
    for (int s = 0; s < 2; s++) {
        const int gy = by + py0 + s;
#pragma unroll
        for (int q = 0; q < 8; q++) {
            int co = co0 + 2*q;
            float lo, hi; unpack2(acc[s][q], lo, hi);
            if (co < BCC)
                g_y2[((n*BCC + co  )*HH + gy)*WW + bx + px] = lo + b[co];
            if (co + 1 < BCC)
                g_y2[((n*BCC + co+1)*HH + gy)*WW + bx + px] = hi + b[co+1];
        }
    }
}

// ---------------- BN stats: partials + finalize (R11 form) -----------------
template<int CH, int WHICH>
__global__ __launch_bounds__(256) void stats_part() {
    const float* y = (WHICH == 0) ? g_y1 : g_y2;
    const int c = blockIdx.x, n = blockIdx.y;
    const int tid = threadIdx.x;
    const float4* p4 = (const float4*)&y[(size_t)(n*CH + c)*NPIX];
    float s = 0.f, s2 = 0.f;
#pragma unroll
    for (int k = 0; k < 4; k++) {
        float4 f = p4[k*256 + tid];
        s  += (f.x + f.y) + (f.z + f.w);
        s2 += (f.x*f.x + f.y*f.y) + (f.z*f.z + f.w*f.w);
    }
    __shared__ float sh[256], sh2[256];
    sh[tid] = s; sh2[tid] = s2;
    __syncthreads();
    for (int st = 128; st > 0; st >>= 1) {
        if (tid < st) { sh[tid] += sh[tid+st]; sh2[tid] += sh2[tid+st]; }
        __syncthreads();
    }
    if (tid == 0) {
        g_part[c*NIMG + n] = sh[0];
        g_part[BCC*NIMG + c*NIMG + n] = sh2[0];
    }
}

template<int CH, int WHICH>
__global__ __launch_bounds__(128) void stats_fin(const float* __restrict__ gam,
                                                 const float* __restrict__ bet) {
    float* ab = (WHICH == 0) ? g_ab1 : g_ab2;
    const int c = threadIdx.x;
    if (c >= CH) return;
    float s = 0.f, s2 = 0.f;
#pragma unroll
    for (int n = 0; n < NIMG; n++) {
        s  += g_part[c*NIMG + n];
        s2 += g_part[BCC*NIMG + c*NIMG + n];
    }
    float mean = s * (1.f/(float)MTOT);
    float var  = s2 * (1.f/(float)MTOT) - mean*mean;
    float a = gam[c] * rsqrtf(var + EPSV);
    ab[2*c]   = a;
    ab[2*c+1] = bet[c] - mean * a;
}

// ---------------- y = tanh(a*y + b) in place; one block per (n,c) ----------
template<int CH, int WHICH>
__global__ __launch_bounds__(256) void bn_tanh_ker() {
    float* y = (WHICH == 0) ? g_y1 : g_y2;
    const float* ab = (WHICH == 0) ? g_ab1 : g_ab2;
    const int c = blockIdx.x % CH;
    const float a = ab[2*c], b = ab[2*c+1];
    float4* p4 = (float4*)y + (size_t)blockIdx.x * 1024;
#pragma unroll
    for (int k = 0; k < 4; k++) {
        float4 f = p4[k*256 + threadIdx.x];
        f.x = tanhf(fmaf(a, f.x, b));
        f.y = tanhf(fmaf(a, f.y, b));
        f.z = tanhf(fmaf(a, f.z, b));
        f.w = tanhf(fmaf(a, f.w, b));
        p4[k*256 + threadIdx.x] = f;
    }
}

// -------- fused: coef -> atoms -> 7x7 patch contraction --------------------
// smem union: coef (phase B input) and xt (phase C input) share storage.
__global__ __launch_bounds__(256) void atoms_ker(const float* __restrict__ x,
                                                 const float* __restrict__ bases) {
    __shared__ __align__(16) float atm [16*49*6];   // 18.8 KB
    __shared__ __align__(16) float bs2 [49*TBAS];   //  3.5 KB
    __shared__ __align__(16) float un  [112*XSTR];  // 21.1 KB
    float* coef = un;
    float* xt   = un;
    const int tid = threadIdx.x;
    const int n  = blockIdx.z;
    const int bx = blockIdx.x * 8;
    const int by = blockIdx.y * 2;

    for (int i = tid; i < 49*TBAS; i += 256) {
        int k = i / TBAS, t = i % TBAS;
        bs2[i] = bases[t*49 + k];
    }
    // stage coef: pixel-inner -> coalesced (16 px of one channel per 16 lanes)
    for (int i = tid; i < 16*108; i += 256) {
        int cc = i >> 4, p = i & 15;
        int py = p >> 3, px = p & 7;
        coef[p*108 + cc] = g_y2[((n*BCC + cc)*HH + (by+py))*WW + (bx+px)];
    }
    __syncthreads();

    // phase B: atoms[p][k][m] = sum_t coef[p][m*18+t] * bases[t][k]
    for (int i = tid; i < 16*49; i += 256) {
        int p = i / 49, k = i % 49;
        const ull* cf = (const ull*)&coef[p*108];
        const ull* bp = (const ull*)&bs2[k*TBAS];
        ull a[6];
#pragma unroll
        for (int m = 0; m < 6; m++) a[m] = 0ull;
#pragma unroll
        for (int u = 0; u < 9; u++) {
            ull bv = bp[u];
#pragma unroll
            for (int m = 0; m < 6; m++)
                a[m] = ffma2(cf[m*9 + u], bv, a[m]);
        }
        float* ap = &atm[(p*49 + k)*6];
#pragma unroll
        for (int m = 0; m < 6; m++) {
            float lo, hi; unpack2(a[m], lo, hi);
            ap[m] = lo + hi;
        }
    }
    __syncthreads();

    // stage xt (overwrites coef): 14x8 halo x 32 ch, stride XSTR
    for (int i = tid; i < 32*112; i += 256) {
        int c = i / 112, pos = i % 112;
        int yy = pos / 14, xx = pos % 14;
        int gy = by + yy - 3, gx = bx + xx - 3;
        float v = 0.f;
        if (gy >= 0 && gy < HH && gx >= 0 && gx < WW)
            v = x[((n*CINC + c)*HH + gy)*WW + gx];
        xt[pos*XSTR + c] = v;
    }
    __syncthreads();

    // phase C: thread = (pixel pg, channels {cl, cl+16}); 6 m each.
    {
        const int pg = tid >> 4, cl = tid & 15;
        const int py = pg >> 3, px = pg & 7;
        const float* ab_ = &atm[pg*49*6];
        const float* xb  = &xt[(py*14 + px)*XSTR];
        ull a0[3], a1[3];
#pragma unroll
        for (int m = 0; m < 3; m++) { a0[m] = 0ull; a1[m] = 0ull; }
#pragma unroll
        for (int ky = 0; ky < 7; ky++) {
#pragma unroll
            for (int kx = 0; kx < 7; kx++) {
                const int k = ky*7 + kx;
                const int off = (ky*14 + kx)*XSTR;
                float v0 = xb[off + cl];
                float v1 = xb[off + cl + 16];
                ull x0 = pack2(v0, v0);
                ull x1 = pack2(v1, v1);
                const ull* ap = (const ull*)&ab_[k*6];
                ull p0 = ap[0], p1 = ap[1], p2 = ap[2];
                a0[0] = ffma2(p0, x0, a0[0]);
                a0[1] = ffma2(p1, x0, a0[1]);
                a0[2] = ffma2(p2, x0, a0[2]);
                a1[0] = ffma2(p0, x1, a1[0]);
                a1[1] = ffma2(p1, x1, a1[1]);
                a1[2] = ffma2(p2, x1, a1[2]);
            }
        }
        const int gy = by + py, gx = bx + px;
        const long pix = (long)n*NPIX + gy*WW + gx;
        ull* op0 = (ull*)&g_bout[pix*192 + cl*6];
        op0[0] = a0[0]; op0[1] = a0[1]; op0[2] = a0[2];
        ull* op1 = (ull*)&g_bout[pix*192 + (cl+16)*6];
        op1[0] = a1[0]; op1[1] = a1[1]; op1[2] = a1[2];
    }
}

// ---------------- out projection: out = W(64,192) . bout + b ---------------
__global__ __launch_bounds__(256) void out_ker(const float* __restrict__ ow,
                                               const float* __restrict__ ob,
                                               float* __restrict__ out) {
    __shared__ __align__(16) float wt2[48*64];   // [dl][o]
    __shared__ __align__(16) float bt[128*49];   // [pix][dl], pad 49
    const int pix0 = blockIdx.x * 128;
    const int tid = threadIdx.x;
    const int pix = tid & 63, og = tid >> 6;

    ull accA[8], accB[8];
#pragma unroll
    for (int i = 0; i < 8; i++) { accA[i] = 0ull; accB[i] = 0ull; }

    for (int ch = 0; ch < 4; ch++) {
        const int d0 = ch * 48;
        for (int i = tid; i < 48*64; i += 256) {
            int dl = i >> 6, o = i & 63;
            wt2[i] = ow[o*192 + d0 + dl];
        }
        for (int i = tid; i < 128*12; i += 256) {
            int p = i / 12, v = i % 12;
            float4 f = ((const float4*)&g_bout[(long)(pix0 + p)*192 + d0])[v];
            float* dst = &bt[p*49 + v*4];
            dst[0] = f.x; dst[1] = f.y; dst[2] = f.z; dst[3] = f.w;
        }
        __syncthreads();
#pragma unroll 4
        for (int dl = 0; dl < 48; dl++) {
            float bvA = bt[pix*49 + dl];
            float bvB = bt[(pix+64)*49 + dl];
            ull bA = pack2(bvA, bvA);
            ull bB = pack2(bvB, bvB);
            const ulonglong2* wp = (const ulonglong2*)&wt2[dl*64 + og*16];
#pragma unroll
            for (int q = 0; q < 4; q++) {
                ulonglong2 u = wp[q];
                accA[2*q  ] = ffma2(u.x, bA, accA[2*q  ]);
                accA[2*q+1] = ffma2(u.y, bA, accA[2*q+1]);
                accB[2*q  ] = ffma2(u.x, bB, accB[2*q  ]);
                accB[2*q+1] = ffma2(u.y, bB, accB[2*q+1]);
            }
        }
        __syncthreads();
    }
    const int n = pix0 >> 12;
    const int remA = (pix0 & 4095) + pix;
    const int remB = remA + 64;
#pragma unroll
    for (int i = 0; i < 8; i++) {
        int o = og*16 + 2*i;
        float lo, hi;
        unpack2(accA[i], lo, hi);
        out[((n*OUTC + o  )*NPIX) + remA] = lo + ob[o];
        out[((n*OUTC + o+1)*NPIX) + remA] = hi + ob[o+1];
        unpack2(accB[i], lo, hi);
        out[((n*OUTC + o  )*NPIX) + remB] = lo + ob[o];
        out[((n*OUTC + o+1)*NPIX) + remB] = hi + ob[o+1];
    }
}

// ---------------------------------------------------------------------------
extern "C" void kernel_launch(void* const* d_in, const int* in_sizes, int n_in,
                              void* d_out, int out_size) {
    const float* x   = (const float*)d_in[0];
    const float* w1  = (const float*)d_in[1];
    const float* b1  = (const float*)d_in[2];
    const float* g1  = (const float*)d_in[3];
    const float* bb1 = (const float*)d_in[4];
    const float* w2  = (const float*)d_in[5];
    const float* b2  = (const float*)d_in[6];
    const float* g2  = (const float*)d_in[7];
    const float* bb2 = (const float*)d_in[8];
    const float* bas = (const float*)d_in[9];
    const float* ow  = (const float*)d_in[10];
    const float* ob  = (const float*)d_in[11];
    float* out = (float*)d_out;

    conv1_ker<<<dim3(2, 8, NIMG*4), 128>>>(x, w1, b1);
    stats_part<INTER, 0><<<dim3(INTER, NIMG), 256>>>();
    stats_fin<INTER, 0><<<1, 128>>>(g1, bb1);
    bn_tanh_ker<INTER, 0><<<NIMG*INTER, 256>>>();
    conv2_ker<<<dim3(2, 8, NIMG*7), 128>>>(w2, b2);
    stats_part<BCC, 1><<<dim3(BCC, NIMG), 256>>>();
    stats_fin<BCC, 1><<<1, 128>>>(g2, bb2);
    bn_tanh_ker<BCC, 1><<<NIMG*BCC, 256>>>();
    atoms_ker<<<dim3(8, 32, NIMG), 256>>>(x, bas);
    out_ker<<<256, 256>>>(ow, ob, out);
}